// round 4
// baseline (speedup 1.0000x reference)
#include <cuda_runtime.h>

#define HD     64
#define VOC    64
#define HALF   32
#define BATCH  128
#define SEQLEN 2048

// ---- scratch tables (device globals; no allocation allowed) ----
__device__ float g_ks[VOC * HALF];
__device__ float g_ke[VOC * HALF];
__device__ float g_inv_s[VOC];
__device__ float g_inv_e[VOC];
__device__ float g_Ds[VOC * VOC];   // D[v1][v2] = ks(v1) . ks(v2)
__device__ float g_De[VOC * VOC];   // D[v1][v2] = ke(v1) . ke(v2)

typedef unsigned long long u64;

// Packed f32x2 ops (Blackwell FFMA2 path — only reachable via PTX)
__device__ __forceinline__ u64 ffma2(u64 a, u64 b, u64 c) {
    u64 d;
    asm("fma.rn.f32x2 %0, %1, %2, %3;" : "=l"(d) : "l"(a), "l"(b), "l"(c));
    return d;
}
__device__ __forceinline__ u64 fadd2(u64 a, u64 b) {
    u64 d;
    asm("add.rn.f32x2 %0, %1, %2;" : "=l"(d) : "l"(a), "l"(b));
    return d;
}
__device__ __forceinline__ u64 pack2(float x, float y) {
    u64 r;
    asm("mov.b64 %0, {%1, %2};" : "=l"(r) : "f"(x), "f"(y));
    return r;
}
__device__ __forceinline__ float2 unpack2(u64 v) {
    float x, y;
    asm("mov.b64 {%0, %1}, %2;" : "=f"(x), "=f"(y) : "l"(v));
    return make_float2(x, y);
}

// ============================================================================
// Kernel A: per-vocab-id table precompute (h depends only on token id).
// ============================================================================
__global__ void precompute_kernel(
    const float* __restrict__ embed,
    const float* __restrict__ W1, const float* __restrict__ b1,
    const float* __restrict__ W2, const float* __restrict__ b2,
    const float* __restrict__ ln_g, const float* __restrict__ ln_b,
    const float* __restrict__ Ws, const float* __restrict__ bs,
    const float* __restrict__ We, const float* __restrict__ be)
{
    const int v = blockIdx.x;
    const int t = threadIdx.x;

    __shared__ float s_e[HD];
    __shared__ float s_a[2 * HD];
    __shared__ float s_x[HD];
    __shared__ float s_h[HD];
    __shared__ float s_kv[2 * HALF];

    if (t < HD) s_e[t] = embed[v * HD + t];
    __syncthreads();

    {   // hidden = relu(e @ W1 + b1), 128 units, one per thread
        float acc = b1[t];
        #pragma unroll
        for (int d = 0; d < HD; d++)
            acc = fmaf(s_e[d], W1[d * (2 * HD) + t], acc);
        s_a[t] = fmaxf(acc, 0.0f);
    }
    __syncthreads();

    if (t < HD) {   // ff = hidden @ W2 + b2 ; x = e + ff
        float f = b2[t];
        #pragma unroll
        for (int k = 0; k < 2 * HD; k++)
            f = fmaf(s_a[k], W2[k * HD + t], f);
        s_x[t] = s_e[t] + f;
    }
    __syncthreads();

    if (t < HD) {   // LayerNorm (redundant per thread — tiny)
        float mu = 0.0f;
        #pragma unroll
        for (int d = 0; d < HD; d++) mu += s_x[d];
        mu *= (1.0f / HD);
        float var = 0.0f;
        #pragma unroll
        for (int d = 0; d < HD; d++) {
            float dd = s_x[d] - mu;
            var = fmaf(dd, dd, var);
        }
        var *= (1.0f / HD);
        float r = 1.0f / sqrtf(var + 1e-5f);
        s_h[t] = fmaf((s_x[t] - mu) * r, ln_g[t], ln_b[t]);
    }
    __syncthreads();

    if (t < HALF) {             // k_sem = h @ Ws + bs
        float k = bs[t];
        #pragma unroll
        for (int d = 0; d < HD; d++)
            k = fmaf(s_h[d], Ws[d * HALF + t], k);
        g_ks[v * HALF + t] = k;
        s_kv[t] = k;
    } else if (t < 2 * HALF) {  // k_epi = h @ We + be
        const int j = t - HALF;
        float k = be[j];
        #pragma unroll
        for (int d = 0; d < HD; d++)
            k = fmaf(s_h[d], We[d * HALF + j], k);
        g_ke[v * HALF + j] = k;
        s_kv[t] = k;
    }
    __syncthreads();

    if (t == 0) {               // 1/(k.k + 1e-6)
        float den = 1e-6f;
        #pragma unroll
        for (int j = 0; j < HALF; j++) den = fmaf(s_kv[j], s_kv[j], den);
        g_inv_s[v] = 1.0f / den;
    } else if (t == 1) {
        float den = 1e-6f;
        #pragma unroll
        for (int j = 0; j < HALF; j++) den = fmaf(s_kv[HALF + j], s_kv[HALF + j], den);
        g_inv_e[v] = 1.0f / den;
    }
}

// ============================================================================
// Kernel A2: token-pair dot tables D[v1][v2] = k(v1).k(v2) per memory.
// ============================================================================
__global__ void dots_kernel()
{
    const int v1  = blockIdx.x;
    const int tid = threadIdx.x;
    const int v2  = tid & 63;
    const int mem = tid >> 6;

    const float* tab = mem ? g_ke : g_ks;
    float d = 0.0f;
    #pragma unroll
    for (int j = 0; j < HALF; j++)
        d = fmaf(tab[v1 * HALF + j], tab[v2 * HALF + j], d);
    (mem ? g_De : g_Ds)[v1 * VOC + v2] = d;
}

// ============================================================================
// Kernel B: the scan, blocked T=4 with a row-parallel triangular solve.
// 128 blocks (one per batch), 4 warps: warps 0,1 -> M_sem halves, 2,3 -> M_epi.
// 2 lanes/row (lane&1 = 16-col half). Per 4-token block:
//   P_i = M_0 @ k_i          (4x parallel matvecs against the SAME M)
//   vps_i = P_i + sum_{j<i} u_j D[v_j][v_i]   (scalar triangular, ~7-FMA chain)
//   u_i  = fma(-vps_i, inv_i*w_i, kown_i*w_i)
//   M   += sum_i u_i (x) k_i (4x parallel rank-1s)
// The last block's vps_3 at position 2047 IS ctx = M_2046 @ q.
// ============================================================================
__global__ void __launch_bounds__(128, 1) scan_kernel(
    const int* __restrict__ seq,
    const float* __restrict__ Wo,
    const float* __restrict__ bo,
    float* __restrict__ out)
{
    extern __shared__ int smem_raw[];
    int*   s_toko = smem_raw;                        // 2048 ints (byte offsets)
    float* s_k    = (float*)(s_toko + SEQLEN);       // 2 * 2048 floats
    float* s_inv  = s_k + 2 * VOC * HALF;            // 2 * 64
    float* s_D    = s_inv + 2 * VOC;                 // 2 * 4096
    float* s_ctx  = s_D + 2 * VOC * VOC;             // 64

    const int b    = blockIdx.x;
    const int tid  = threadIdx.x;
    const int wid  = tid >> 5;
    const int lane = tid & 31;
    const int mem   = wid >> 1;          // 0 = sem, 1 = epi
    const int whalf = wid & 1;
    const int row   = whalf * 16 + (lane >> 1);
    const int ch    = lane & 1;          // 16-column half

    for (int i = tid; i < SEQLEN; i += 128)
        s_toko[i] = seq[b * SEQLEN + i] << 7;        // byte offset: tok*128
    for (int i = tid; i < VOC * HALF; i += 128) {
        s_k[i]              = g_ks[i];
        s_k[VOC * HALF + i] = g_ke[i];
    }
    for (int i = tid; i < VOC * VOC; i += 128) {
        s_D[i]             = g_Ds[i];
        s_D[VOC * VOC + i] = g_De[i];
    }
    if (tid < VOC) {
        s_inv[tid]       = g_inv_s[tid];
        s_inv[VOC + tid] = g_inv_e[tid];
    }
    __syncthreads();

    const float* ktab  = s_k + mem * (VOC * HALF);
    const char*  kb_ch = (const char*)ktab + ch * 64;          // + tok*128
    const char*  kob   = (const char*)ktab + row * 4;          // kown base
    const char*  Db    = (const char*)(s_D + mem * (VOC * VOC));
    const char*  ivb   = (const char*)(s_inv + mem * VOC);
    const int4*  s_tok4 = (const int4*)s_toko;                 // 512 packs

    const u64 zero64 = 0ull;
    u64 m[8];
    #pragma unroll
    for (int j = 0; j < 8; j++) m[j] = 0ull;

    // recency weight: epi w_t = (t+1)/2048 (update only); sem w = 1
    const float wstep = mem ? (1.0f / 2048.0f) : 0.0f;
    float wt = mem ? (1.0f / 2048.0f) : 1.0f;      // weight of token 4*blk+0

    float ctxv = 0.0f;

    for (int blk = 0; blk < SEQLEN / 4; blk++) {
        const int4 off4 = s_tok4[blk];   // byte offsets of the 4 tokens
        const int o0 = off4.x, o1 = off4.y, o2 = off4.z, o3 = off4.w;

        // ---- load the 4 K tiles (this lane's 16-col half, 4x LDS.128 each)
        u64 k0[8], k1[8], k2[8], k3[8];
        {
            const char* p0 = kb_ch + o0; const char* p1 = kb_ch + o1;
            const char* p2 = kb_ch + o2; const char* p3 = kb_ch + o3;
            #pragma unroll
            for (int j = 0; j < 4; j++) {
                ulonglong2 a = *(const ulonglong2*)(p0 + j * 16);
                ulonglong2 c = *(const ulonglong2*)(p1 + j * 16);
                ulonglong2 e = *(const ulonglong2*)(p2 + j * 16);
                ulonglong2 g = *(const ulonglong2*)(p3 + j * 16);
                k0[2*j] = a.x; k0[2*j+1] = a.y;
                k1[2*j] = c.x; k1[2*j+1] = c.y;
                k2[2*j] = e.x; k2[2*j+1] = e.y;
                k3[2*j] = g.x; k3[2*j+1] = g.y;
            }
        }

        // ---- scalar tables for the block
        const float ko0 = *(const float*)(kob + o0);
        const float ko1 = *(const float*)(kob + o1);
        const float ko2 = *(const float*)(kob + o2);
        const float ko3 = *(const float*)(kob + o3);
        const float iv0 = *(const float*)(ivb + (o0 >> 5));
        const float iv1 = *(const float*)(ivb + (o1 >> 5));
        const float iv2 = *(const float*)(ivb + (o2 >> 5));
        const float iv3 = *(const float*)(ivb + (o3 >> 5));
        const float D01 = *(const float*)(Db + (o0 << 1) + (o1 >> 5));
        const float D02 = *(const float*)(Db + (o0 << 1) + (o2 >> 5));
        const float D03 = *(const float*)(Db + (o0 << 1) + (o3 >> 5));
        const float D12 = *(const float*)(Db + (o1 << 1) + (o2 >> 5));
        const float D13 = *(const float*)(Db + (o1 << 1) + (o3 >> 5));
        const float D23 = *(const float*)(Db + (o2 << 1) + (o3 >> 5));

        const float w0 = wt;
        const float w1 = w0 + wstep;
        const float w2 = w1 + wstep;
        const float w3 = w2 + wstep;
        wt = w3 + wstep;
        const float kw0 = ko0 * w0, iw0 = iv0 * w0;
        const float kw1 = ko1 * w1, iw1 = iv1 * w1;
        const float kw2 = ko2 * w2, iw2 = iv2 * w2;
        const float kw3 = ko3 * w3, iw3 = iv3 * w3;

        // ---- phase 1: P_i = M_0 @ k_i (4 independent matvecs, 2 accums each)
        u64 a0 = ffma2(m[0], k0[0], zero64), b0 = ffma2(m[1], k0[1], zero64);
        u64 a1 = ffma2(m[0], k1[0], zero64), b1 = ffma2(m[1], k1[1], zero64);
        u64 a2 = ffma2(m[0], k2[0], zero64), b2 = ffma2(m[1], k2[1], zero64);
        u64 a3 = ffma2(m[0], k3[0], zero64), b3 = ffma2(m[1], k3[1], zero64);
        #pragma unroll
        for (int j = 2; j < 8; j += 2) {
            a0 = ffma2(m[j], k0[j], a0); b0 = ffma2(m[j+1], k0[j+1], b0);
            a1 = ffma2(m[j], k1[j], a1); b1 = ffma2(m[j+1], k1[j+1], b1);
            a2 = ffma2(m[j], k2[j], a2); b2 = ffma2(m[j+1], k2[j+1], b2);
            a3 = ffma2(m[j], k3[j], a3); b3 = ffma2(m[j+1], k3[j+1], b3);
        }
        float2 r0 = unpack2(fadd2(a0, b0));
        float2 r1 = unpack2(fadd2(a1, b1));
        float2 r2 = unpack2(fadd2(a2, b2));
        float2 r3 = unpack2(fadd2(a3, b3));
        float p0 = r0.x + r0.y;
        float p1 = r1.x + r1.y;
        float p2 = r2.x + r2.y;
        float p3 = r3.x + r3.y;
        p0 += __shfl_xor_sync(0xffffffffu, p0, 1);
        p1 += __shfl_xor_sync(0xffffffffu, p1, 1);
        p2 += __shfl_xor_sync(0xffffffffu, p2, 1);
        p3 += __shfl_xor_sync(0xffffffffu, p3, 1);

        // ---- phase 2: triangular solve (row-parallel scalars)
        const float u0 = fmaf(-p0, iw0, kw0);
        float vps1 = fmaf(u0, D01, p1);
        const float u1 = fmaf(-vps1, iw1, kw1);
        float vps2 = fmaf(u0, D02, p2);
        vps2 = fmaf(u1, D12, vps2);
        const float u2 = fmaf(-vps2, iw2, kw2);
        float vps3 = fmaf(u0, D03, p3);
        vps3 = fmaf(u1, D13, vps3);
        vps3 = fmaf(u2, D23, vps3);
        const float u3 = fmaf(-vps3, iw3, kw3);
        ctxv = vps3;                       // last block: = (M_2046 @ q)[row]

        // ---- phase 3: M += sum_i u_i (x) k_i
        const u64 U0 = pack2(u0, u0);
        const u64 U1 = pack2(u1, u1);
        const u64 U2 = pack2(u2, u2);
        const u64 U3 = pack2(u3, u3);
        #pragma unroll
        for (int j = 0; j < 8; j++) {
            u64 t0 = ffma2(U0, k0[j], m[j]);
            t0 = ffma2(U1, k1[j], t0);
            t0 = ffma2(U2, k2[j], t0);
            m[j] = ffma2(U3, k3[j], t0);
        }
    }

    // ctxv (post-shfl; both lanes of a row agree) = ctx[row] for this memory.
    // Note: the final block applied u3 (position 2047) to M, but M is dead.
    if (ch == 0) s_ctx[mem * HALF + row] = ctxv;
    __syncthreads();

    if (tid < VOC) {
        float o = bo[tid];
        #pragma unroll
        for (int i = 0; i < 2 * HALF; i++)
            o = fmaf(s_ctx[i], Wo[i * VOC + tid], o);
        out[b * VOC + tid] = o;
    }
}

// ============================================================================
// Launch. Inputs in metadata order:
// 0:seq 1:embed 2:W1 3:b1 4:W2 5:b2 6:ln_g 7:ln_b 8:Ws 9:bs 10:We 11:be 12:Wo 13:bo
// ============================================================================
#define SCAN_SMEM_BYTES ((SEQLEN + 2*VOC*HALF + 2*VOC + 2*VOC*VOC + VOC) * 4)

extern "C" void kernel_launch(void* const* d_in, const int* in_sizes, int n_in,
                              void* d_out, int out_size)
{
    const int*   seq   = (const int*)  d_in[0];
    const float* embed = (const float*)d_in[1];
    const float* W1    = (const float*)d_in[2];
    const float* b1    = (const float*)d_in[3];
    const float* W2    = (const float*)d_in[4];
    const float* b2    = (const float*)d_in[5];
    const float* ln_g  = (const float*)d_in[6];
    const float* ln_b  = (const float*)d_in[7];
    const float* Ws    = (const float*)d_in[8];
    const float* bs    = (const float*)d_in[9];
    const float* We    = (const float*)d_in[10];
    const float* be    = (const float*)d_in[11];
    const float* Wo    = (const float*)d_in[12];
    const float* bo    = (const float*)d_in[13];

    cudaFuncSetAttribute(scan_kernel,
                         cudaFuncAttributeMaxDynamicSharedMemorySize,
                         SCAN_SMEM_BYTES);

    precompute_kernel<<<VOC, 128>>>(embed, W1, b1, W2, b2, ln_g, ln_b,
                                    Ws, bs, We, be);
    dots_kernel<<<VOC, 128>>>();
    scan_kernel<<<BATCH, 128, SCAN_SMEM_BYTES>>>(seq, Wo, bo, (float*)d_out);
}